// round 15
// baseline (speedup 1.0000x reference)
#include <cuda_runtime.h>
#include <cuda_bf16.h>
#include <cstdint>
#include <math.h>

// Problem constants
#define Bb 4
#define Tt 2048
#define Cc 1024
#define Hh 16
#define Dd 64
#define BT (Bb*Tt)          // 8192
#define C3 (3*Cc)           // 3072

// 0.125 * log2(e): folded into K so softmax runs in exp2 domain
#define KSCALE 0.18033688011112042f

// ---------------------------------------------------------------------------
// Scratch (no cudaMalloc allowed)
// ---------------------------------------------------------------------------
__device__ __nv_bfloat16 g_qkvh[BT * C3];        // roped qkv hi (K pre-scaled)
__device__ __nv_bfloat16 g_qkvl[BT * C3];        // roped qkv lo
__device__ __nv_bfloat16 g_xhi[BT * Cc];         // x split
__device__ __nv_bfloat16 g_xlo[BT * Cc];
__device__ __nv_bfloat16 g_wq_hi[C3 * Cc];       // W_qkv^T split  [N=3072][K=1024]
__device__ __nv_bfloat16 g_wq_lo[C3 * Cc];
__device__ __nv_bfloat16 g_wp_hi[Cc * Cc];       // W_proj^T split [N=1024][K=1024]
__device__ __nv_bfloat16 g_wp_lo[Cc * Cc];
__device__ __nv_bfloat16 g_yhi[BT * Cc];         // attention out split
__device__ __nv_bfloat16 g_ylo[BT * Cc];
__device__ float2 g_rope[Tt * 32];               // (sin, cos) per (t, i)

// ---------------------------------------------------------------------------
// Warp MMA helpers (plain sm_80+ features — no arch-suffix gating)
// ---------------------------------------------------------------------------
__device__ __forceinline__ uint32_t smem_to_u32(const void* p) {
    uint32_t a;
    asm("{ .reg .u64 t; cvta.to.shared.u64 t, %1; cvt.u32.u64 %0, t; }"
        : "=r"(a) : "l"(p));
    return a;
}
__device__ __forceinline__ void cp16(uint32_t d, const void* s) {
    asm volatile("cp.async.cg.shared.global [%0], [%1], 16;\n"
                 :: "r"(d), "l"(s) : "memory");
}
#define CP_COMMIT() asm volatile("cp.async.commit_group;" ::: "memory")
#define CP_WAIT(n)  asm volatile("cp.async.wait_group %0;" :: "n"(n) : "memory")

__device__ __forceinline__ void ldm_x4(uint32_t* r, uint32_t addr) {
    asm volatile("ldmatrix.sync.aligned.m8n8.x4.shared.b16 {%0,%1,%2,%3}, [%4];"
                 : "=r"(r[0]), "=r"(r[1]), "=r"(r[2]), "=r"(r[3]) : "r"(addr));
}
__device__ __forceinline__ void ldm_x4_t(uint32_t* r, uint32_t addr) {
    asm volatile("ldmatrix.sync.aligned.m8n8.x4.trans.shared.b16 {%0,%1,%2,%3}, [%4];"
                 : "=r"(r[0]), "=r"(r[1]), "=r"(r[2]), "=r"(r[3]) : "r"(addr));
}
__device__ __forceinline__ void mma_bf16(float* d, const uint32_t* a,
                                         const uint32_t* b) {
    asm volatile(
        "mma.sync.aligned.m16n8k16.row.col.f32.bf16.bf16.f32 "
        "{%0,%1,%2,%3}, {%4,%5,%6,%7}, {%8,%9}, {%0,%1,%2,%3};"
        : "+f"(d[0]), "+f"(d[1]), "+f"(d[2]), "+f"(d[3])
        : "r"(a[0]), "r"(a[1]), "r"(a[2]), "r"(a[3]), "r"(b[0]), "r"(b[1]));
}
// split two floats into packed bf16x2 hi + lo (residual)
__device__ __forceinline__ void split2(float a, float b, uint32_t& hi, uint32_t& lo) {
    __nv_bfloat16 ha = __float2bfloat16(a), hb = __float2bfloat16(b);
    __nv_bfloat16 la = __float2bfloat16(a - __bfloat162float(ha));
    __nv_bfloat16 lb = __float2bfloat16(b - __bfloat162float(hb));
    __nv_bfloat162 h2(ha, hb), l2(la, lb);
    hi = *(uint32_t*)&h2;
    lo = *(uint32_t*)&l2;
}

// ---------------------------------------------------------------------------
// RoPE sin/cos table
// ---------------------------------------------------------------------------
__global__ void fill_rope() {
    int idx = blockIdx.x * blockDim.x + threadIdx.x;
    if (idx >= Tt * 32) return;
    int t = idx >> 5, i = idx & 31;
    float freq = exp2f(-(float)i * 0.4152410118609203f);
    float sn, cs;
    sincosf((float)t * freq, &sn, &cs);
    g_rope[idx] = make_float2(sn, cs);
}

// ---------------------------------------------------------------------------
// Split-bf16 HMMA GEMM (R9 mainloop — known good).
// MODE 0: out = fp32 + bias.
// MODE 1: rope(acc+bias); K section additionally scaled by KSCALE; bf16 hi/lo.
// ---------------------------------------------------------------------------
#define GPITCH 64
#define GSEC   8192
#define GSTAGE (4 * GSEC)
#define GEMM_SMEM (3 * GSTAGE)         // 98304

template<int MODE>
__global__ __launch_bounds__(256, 2) void gemm_mma(
    const __nv_bfloat16* __restrict__ Ahi, const __nv_bfloat16* __restrict__ Alo,
    const __nv_bfloat16* __restrict__ Bhi, const __nv_bfloat16* __restrict__ Blo,
    const float* __restrict__ bias, float* __restrict__ outF,
    __nv_bfloat16* __restrict__ outH, __nv_bfloat16* __restrict__ outL, int N)
{
    extern __shared__ char sm[];
    const int tid = threadIdx.x, lane = tid & 31, wid = tid >> 5;
    const int warpM = wid >> 1, warpN = wid & 1;
    const int mBase = blockIdx.y * 128, nBase = blockIdx.x * 128;
    const uint32_t smBase = smem_to_u32(sm);

    const int aRow = warpM * 32 + (lane & 15);
    const int aSel = (lane >> 4) & 1;
    const int aSwz = ((lane & 15) >> 1) & 3;
    const int bRow = warpN * 64 + (lane & 7) + ((lane >> 4) & 1) * 8;
    const int bSel = (lane >> 3) & 1;
    const int bSwz = ((((lane & 7) + ((lane >> 4) & 1) * 8)) >> 1) & 3;

    float acc[2][8][4];
    #pragma unroll
    for (int a = 0; a < 2; a++)
        #pragma unroll
        for (int q = 0; q < 8; q++)
            #pragma unroll
            for (int v = 0; v < 4; v++) acc[a][q][v] = 0.f;

    auto ldChunk = [&](int c, int stage) {
        uint32_t base = smBase + stage * GSTAGE;
        const int k0 = c * 32;
        #pragma unroll
        for (int i = 0; i < 2; i++) {
            int idx = i * 256 + tid;
            int row = idx >> 2, s = idx & 3;
            int ps = s ^ ((row >> 1) & 3);
            uint32_t d = base + row * GPITCH + ps * 16;
            size_t ga = (size_t)(mBase + row) * 1024 + k0 + s * 8;
            size_t gb = (size_t)(nBase + row) * 1024 + k0 + s * 8;
            cp16(d,            Ahi + ga);
            cp16(d + GSEC,     Alo + ga);
            cp16(d + 2 * GSEC, Bhi + gb);
            cp16(d + 3 * GSEC, Blo + gb);
        }
    };

    auto compute = [&](int stage) {
        uint32_t base = smBase + stage * GSTAGE;
        #pragma unroll
        for (int k16 = 0; k16 < 2; k16++) {
            const int aC = ((k16 * 2 + aSel) ^ aSwz) * 16;
            const int bC = ((k16 * 2 + bSel) ^ bSwz) * 16;
            uint32_t ah[2][4], al[2][4];
            #pragma unroll
            for (int a = 0; a < 2; a++) {
                uint32_t ad = base + (aRow + a * 16) * GPITCH + aC;
                ldm_x4(ah[a], ad);
                ldm_x4(al[a], ad + GSEC);
            }
            #pragma unroll
            for (int p = 0; p < 4; p++) {
                uint32_t bh[4], bl[4];
                uint32_t bd = base + 2 * GSEC + (bRow + p * 16) * GPITCH + bC;
                ldm_x4(bh, bd);
                ldm_x4(bl, bd + GSEC);
                #pragma unroll
                for (int a = 0; a < 2; a++) {
                    mma_bf16(acc[a][p * 2 + 0], ah[a], bh);
                    mma_bf16(acc[a][p * 2 + 0], ah[a], bl);
                    mma_bf16(acc[a][p * 2 + 0], al[a], bh);
                    mma_bf16(acc[a][p * 2 + 1], ah[a], bh + 2);
                    mma_bf16(acc[a][p * 2 + 1], ah[a], bl + 2);
                    mma_bf16(acc[a][p * 2 + 1], al[a], bh + 2);
                }
            }
        }
    };

    ldChunk(0, 0); CP_COMMIT();
    ldChunk(1, 1); CP_COMMIT();
    #pragma unroll 1
    for (int c = 0; c < 32; c++) {
        if (c == 31) { CP_WAIT(0); } else { CP_WAIT(1); }
        __syncthreads();
        if (c + 2 < 32) {
            ldChunk(c + 2, (c + 2) % 3);
            CP_COMMIT();
        }
        compute(c % 3);
    }

    const int r0 = mBase + warpM * 32 + (lane >> 2);
    #pragma unroll
    for (int a = 0; a < 2; a++)
        #pragma unroll
        for (int p = 0; p < 4; p++)
            #pragma unroll
            for (int h = 0; h < 2; h++) {
                const int col = nBase + warpN * 64 + p * 16 + h * 8 + (lane & 3) * 2;
                float2 bb = *(const float2*)(bias + col);
                #pragma unroll
                for (int r = 0; r < 2; r++) {
                    const int row = r0 + a * 16 + r * 8;
                    float v0 = acc[a][p * 2 + h][2 * r]     + bb.x;
                    float v1 = acc[a][p * 2 + h][2 * r + 1] + bb.y;
                    if (MODE == 1) {
                        if (col < 2048) {   // q or k: RoPE
                            int i = (col & 63) >> 1;
                            int t = row & (Tt - 1);
                            float2 sc = g_rope[t * 32 + i];
                            float u0 = v0 * sc.y - v1 * sc.x;
                            float u1 = v0 * sc.x + v1 * sc.y;
                            v0 = u0; v1 = u1;
                            if (col >= 1024) {   // k: fold softmax scale (exp2 domain)
                                v0 *= KSCALE; v1 *= KSCALE;
                            }
                        }
                        uint32_t hi, lo;
                        split2(v0, v1, hi, lo);
                        size_t off = (size_t)row * N + col;
                        *(uint32_t*)(outH + off) = hi;
                        *(uint32_t*)(outL + off) = lo;
                    } else {
                        float2 o = { v0, v1 };
                        *(float2*)(outF + (size_t)row * N + col) = o;
                    }
                }
            }
}

// ---------------------------------------------------------------------------
// HMMA flash attention, Br=128, Bc=64, 256 threads, 2 CTAs/SM.
// 3-stage KV ring: after Q fragments are lifted to registers, the Q smem
// region (2*FQSZ == FKV bytes) is reused as KV stage 2 — gemm-style
// data-2-ahead pipeline at zero extra smem.
// ---------------------------------------------------------------------------
#define FP 144
#define FQSZ (128 * FP)               // 18432
#define FKSZ (64 * FP)                // 9216
#define FKV  (4 * FKSZ)               // 36864 per stage (== 2*FQSZ)
#define FLASH_SMEM (FKV + 2 * FKV)    // 110592 (Q region + 2 KV stages)

__global__ __launch_bounds__(256, 2) void flash_mma(
    const __nv_bfloat16* __restrict__ qh, const __nv_bfloat16* __restrict__ ql,
    __nv_bfloat16* __restrict__ yh, __nv_bfloat16* __restrict__ yl)
{
    extern __shared__ char sm[];
    const int tid = threadIdx.x, lane = tid & 31, wid = tid >> 5;
    const int bh = blockIdx.y, b = bh >> 4, h = bh & 15;
    const int qt = (gridDim.x - 1) - blockIdx.x;   // heavy CTAs first
    const int q0 = qt * 128;
    const int ntiles = 2 * qt + 2;
    const size_t grow = (size_t)b * Tt;

    const uint32_t QH = smem_to_u32(sm);           // Q region == KV stage 2
    const uint32_t stAddr0 = QH + FKV;             // KV stage 0
    const uint32_t stAddr1 = QH + 2 * FKV;         // KV stage 1

    auto stageAddr = [&](int s) -> uint32_t {
        return (s == 0) ? stAddr0 : (s == 1) ? stAddr1 : QH;
    };

    // prefetch Q (128 rows, hi+lo) into QH region
    {
        #pragma unroll
        for (int i = 0; i < 4; i++) {
            int idx = i * 256 + tid;
            int row = idx >> 3, ch = idx & 7;
            uint32_t d = QH + row * FP + ch * 16;
            size_t src = (grow + q0 + row) * C3 + h * Dd + ch * 8;
            cp16(d,        qh + src);
            cp16(d + FQSZ, ql + src);
        }
    }
    auto prefetchKV = [&](int kt, uint32_t base) {
        #pragma unroll
        for (int i = 0; i < 2; i++) {
            int idx = i * 256 + tid;
            int row = idx >> 3, ch = idx & 7;
            uint32_t d = base + row * FP + ch * 16;
            size_t srcK = (grow + kt * 64 + row) * C3 + Cc + h * Dd + ch * 8;
            size_t srcV = srcK + Cc;
            cp16(d,            qh + srcK);
            cp16(d + FKSZ,     ql + srcK);
            cp16(d + 2 * FKSZ, qh + srcV);
            cp16(d + 3 * FKSZ, ql + srcV);
        }
    };
    prefetchKV(0, stAddr0);
    CP_COMMIT();                        // group: Q + KV0
    prefetchKV(1, stAddr1);
    CP_COMMIT();                        // group: KV1
    CP_WAIT(1);                         // Q + KV0 arrived
    __syncthreads();

    // lift Q fragments into registers, then free the Q smem region
    uint32_t qhf[4][4], qlf[4][4];
    {
        uint32_t a = QH + (wid * 16 + (lane & 15)) * FP + ((lane >> 4) & 1) * 16;
        #pragma unroll
        for (int k16 = 0; k16 < 4; k16++) {
            ldm_x4(qhf[k16], a + k16 * 32);
            ldm_x4(qlf[k16], a + FQSZ + k16 * 32);
        }
    }
    __syncthreads();                    // all warps done reading Q smem

    float o[8][4];
    float mrow[2] = {-1e30f, -1e30f}, lrow[2] = {0.f, 0.f};
    #pragma unroll
    for (int d = 0; d < 8; d++)
        #pragma unroll
        for (int v = 0; v < 4; v++) o[d][v] = 0.f;

    const int rowMin = q0 + wid * 16;
    const int row0g = rowMin + (lane >> 2);

    #pragma unroll 1
    for (int kt = 0; kt < ntiles; kt++) {
        if (kt > 0) {
            if (kt + 1 < ntiles) { CP_WAIT(1); } else { CP_WAIT(0); }
            __syncthreads();
        }
        if (kt + 2 < ntiles) {
            prefetchKV(kt + 2, stageAddr((kt + 2) % 3));
            CP_COMMIT();
        }

        if (kt * 64 > rowMin + 15) continue;   // fully masked for this warp

        const uint32_t KB = stageAddr(kt % 3);

        // ---- S = Q K^T (split; S already in exp2 domain) ----
        float s[8][4];
        #pragma unroll
        for (int n = 0; n < 8; n++)
            #pragma unroll
            for (int v = 0; v < 4; v++) s[n][v] = 0.f;

        #pragma unroll
        for (int k16 = 0; k16 < 4; k16++) {
            #pragma unroll
            for (int np = 0; np < 4; np++) {
                uint32_t kh4[4], kl4[4];
                uint32_t ad = KB + (np * 16 + (lane & 7) + ((lane >> 4) & 1) * 8) * FP
                            + ((lane >> 3) & 1) * 16 + k16 * 32;
                ldm_x4(kh4, ad);
                ldm_x4(kl4, ad + FKSZ);
                mma_bf16(s[2 * np],     qhf[k16], kh4);
                mma_bf16(s[2 * np],     qhf[k16], kl4);
                mma_bf16(s[2 * np],     qlf[k16], kh4);
                mma_bf16(s[2 * np + 1], qhf[k16], kh4 + 2);
                mma_bf16(s[2 * np + 1], qhf[k16], kl4 + 2);
                mma_bf16(s[2 * np + 1], qlf[k16], kh4 + 2);
            }
        }

        // ---- causal mask ----
        if (kt * 64 + 63 > rowMin) {
            #pragma unroll
            for (int n = 0; n < 8; n++) {
                int colg = kt * 64 + n * 8 + (lane & 3) * 2;
                #pragma unroll
                for (int r = 0; r < 2; r++)
                    #pragma unroll
                    for (int j = 0; j < 2; j++)
                        if (colg + j > row0g + r * 8) s[n][2 * r + j] = -1e30f;
            }
        }

        // ---- online softmax in exp2 domain ----
        #pragma unroll
        for (int r = 0; r < 2; r++) {
            float mx = -1e30f;
            #pragma unroll
            for (int n = 0; n < 8; n++)
                mx = fmaxf(mx, fmaxf(s[n][2 * r], s[n][2 * r + 1]));
            mx = fmaxf(mx, __shfl_xor_sync(0xffffffffu, mx, 1));
            mx = fmaxf(mx, __shfl_xor_sync(0xffffffffu, mx, 2));
            float mnew = fmaxf(mrow[r], mx);
            float alpha = exp2f(mrow[r] - mnew);
            float sum = 0.f;
            #pragma unroll
            for (int n = 0; n < 8; n++) {
                float p0 = exp2f(s[n][2 * r] - mnew);
                float p1 = exp2f(s[n][2 * r + 1] - mnew);
                s[n][2 * r] = p0; s[n][2 * r + 1] = p1;
                sum += p0 + p1;
            }
            sum += __shfl_xor_sync(0xffffffffu, sum, 1);
            sum += __shfl_xor_sync(0xffffffffu, sum, 2);
            lrow[r] = lrow[r] * alpha + sum;
            mrow[r] = mnew;
            #pragma unroll
            for (int d = 0; d < 8; d++) {
                o[d][2 * r] *= alpha;
                o[d][2 * r + 1] *= alpha;
            }
        }

        // ---- O += P V (full 3-combo split) ----
        #pragma unroll
        for (int k16 = 0; k16 < 4; k16++) {
            uint32_t phi[4], plo[4];
            const int t0 = 2 * k16, t1 = t0 + 1;
            split2(s[t0][0], s[t0][1], phi[0], plo[0]);
            split2(s[t0][2], s[t0][3], phi[1], plo[1]);
            split2(s[t1][0], s[t1][1], phi[2], plo[2]);
            split2(s[t1][2], s[t1][3], phi[3], plo[3]);
            #pragma unroll
            for (int dp = 0; dp < 4; dp++) {
                uint32_t vh4[4], vl4[4];
                uint32_t ad = KB + 2 * FKSZ
                            + (k16 * 16 + (lane & 7) + ((lane >> 3) & 1) * 8) * FP
                            + ((lane >> 4) & 1) * 16 + dp * 32;
                ldm_x4_t(vh4, ad);
                ldm_x4_t(vl4, ad + FKSZ);
                mma_bf16(o[2 * dp],     phi, vh4);
                mma_bf16(o[2 * dp],     phi, vl4);
                mma_bf16(o[2 * dp],     plo, vh4);
                mma_bf16(o[2 * dp + 1], phi, vh4 + 2);
                mma_bf16(o[2 * dp + 1], phi, vl4 + 2);
                mma_bf16(o[2 * dp + 1], plo, vh4 + 2);
            }
        }
    }

    // ---- epilogue ----
    #pragma unroll
    for (int r = 0; r < 2; r++) {
        const int t = q0 + wid * 16 + (lane >> 2) + r * 8;
        const float inv = 1.f / lrow[r];
        const size_t ro = (grow + t) * Cc + h * Dd;
        #pragma unroll
        for (int d = 0; d < 8; d++) {
            int col = d * 8 + (lane & 3) * 2;
            float v0 = o[d][2 * r] * inv;
            float v1 = o[d][2 * r + 1] * inv;
            uint32_t hi, lo;
            split2(v0, v1, hi, lo);
            *(uint32_t*)(yh + ro + col) = hi;
            *(uint32_t*)(yl + ro + col) = lo;
        }
    }
}

// ---------------------------------------------------------------------------
// fp32 -> (hi, lo) bf16 split
// ---------------------------------------------------------------------------
__global__ __launch_bounds__(256) void split_bf16(
    const float* __restrict__ x, __nv_bfloat16* __restrict__ hi,
    __nv_bfloat16* __restrict__ lo, int n4)
{
    int i = blockIdx.x * blockDim.x + threadIdx.x;
    if (i >= n4) return;
    float4 v = ((const float4*)x)[i];
    __nv_bfloat16 h0 = __float2bfloat16(v.x);
    __nv_bfloat16 h1 = __float2bfloat16(v.y);
    __nv_bfloat16 h2 = __float2bfloat16(v.z);
    __nv_bfloat16 h3 = __float2bfloat16(v.w);
    __nv_bfloat16 l0 = __float2bfloat16(v.x - __bfloat162float(h0));
    __nv_bfloat16 l1 = __float2bfloat16(v.y - __bfloat162float(h1));
    __nv_bfloat16 l2 = __float2bfloat16(v.z - __bfloat162float(h2));
    __nv_bfloat16 l3 = __float2bfloat16(v.w - __bfloat162float(h3));
    __nv_bfloat162* hp = (__nv_bfloat162*)(hi + i * 4);
    __nv_bfloat162* lp = (__nv_bfloat162*)(lo + i * 4);
    hp[0] = __nv_bfloat162(h0, h1); hp[1] = __nv_bfloat162(h2, h3);
    lp[0] = __nv_bfloat162(l0, l1); lp[1] = __nv_bfloat162(l2, l3);
}

// ---------------------------------------------------------------------------
// W [K, N] fp32 -> Wt hi/lo bf16 [N, K] (transpose + split)
// ---------------------------------------------------------------------------
__global__ __launch_bounds__(256) void transpose_split(
    const float* __restrict__ W, __nv_bfloat16* __restrict__ thi,
    __nv_bfloat16* __restrict__ tlo, int K, int N)
{
    __shared__ float t[32][33];
    const int k0 = blockIdx.y * 32, n0 = blockIdx.x * 32;
    const int x = threadIdx.x, y = threadIdx.y;   // block (32, 8)
    #pragma unroll
    for (int r = 0; r < 32; r += 8)
        t[y + r][x] = W[(size_t)(k0 + y + r) * N + n0 + x];
    __syncthreads();
    #pragma unroll
    for (int r = 0; r < 32; r += 8) {
        float v = t[x][y + r];
        __nv_bfloat16 h = __float2bfloat16(v);
        __nv_bfloat16 l = __float2bfloat16(v - __bfloat162float(h));
        size_t o = (size_t)(n0 + y + r) * K + k0 + x;
        thi[o] = h; tlo[o] = l;
    }
}

// ---------------------------------------------------------------------------
extern "C" void kernel_launch(void* const* d_in, const int* in_sizes, int n_in,
                              void* d_out, int out_size)
{
    const float* x      = (const float*)d_in[0];
    const float* W_qkv  = (const float*)d_in[1];
    const float* b_qkv  = (const float*)d_in[2];
    const float* W_proj = (const float*)d_in[3];
    const float* b_proj = (const float*)d_in[4];
    float* out = (float*)d_out;

    void *qh_p, *ql_p, *xh_p, *xl_p, *wqh_p, *wql_p, *wph_p, *wpl_p,
         *yh_p, *yl_p;
    cudaGetSymbolAddress(&qh_p, g_qkvh);
    cudaGetSymbolAddress(&ql_p, g_qkvl);
    cudaGetSymbolAddress(&xh_p, g_xhi);
    cudaGetSymbolAddress(&xl_p, g_xlo);
    cudaGetSymbolAddress(&wqh_p, g_wq_hi);
    cudaGetSymbolAddress(&wql_p, g_wq_lo);
    cudaGetSymbolAddress(&wph_p, g_wp_hi);
    cudaGetSymbolAddress(&wpl_p, g_wp_lo);
    cudaGetSymbolAddress(&yh_p, g_yhi);
    cudaGetSymbolAddress(&yl_p, g_ylo);

    cudaFuncSetAttribute(gemm_mma<0>,
        cudaFuncAttributeMaxDynamicSharedMemorySize, GEMM_SMEM);
    cudaFuncSetAttribute(gemm_mma<1>,
        cudaFuncAttributeMaxDynamicSharedMemorySize, GEMM_SMEM);
    cudaFuncSetAttribute(flash_mma,
        cudaFuncAttributeMaxDynamicSharedMemorySize, FLASH_SMEM);

    // 0) RoPE sin/cos table
    fill_rope<<<(Tt * 32 + 255) / 256, 256>>>();
    // 1) Split x -> bf16 hi/lo
    split_bf16<<<(BT * Cc / 4 + 255) / 256, 256>>>(
        x, (__nv_bfloat16*)xh_p, (__nv_bfloat16*)xl_p, BT * Cc / 4);
    // 2) Transpose+split weights
    {
        dim3 g(C3 / 32, Cc / 32);
        transpose_split<<<g, dim3(32, 8)>>>(W_qkv,
            (__nv_bfloat16*)wqh_p, (__nv_bfloat16*)wql_p, Cc, C3);
    }
    {
        dim3 g(Cc / 32, Cc / 32);
        transpose_split<<<g, dim3(32, 8)>>>(W_proj,
            (__nv_bfloat16*)wph_p, (__nv_bfloat16*)wpl_p, Cc, Cc);
    }
    // 3) QKV GEMM + fused RoPE + K-scale + split -> qkvh/qkvl bf16
    {
        dim3 grid(C3 / 128, BT / 128);
        gemm_mma<1><<<grid, 256, GEMM_SMEM>>>(
            (const __nv_bfloat16*)xh_p, (const __nv_bfloat16*)xl_p,
            (const __nv_bfloat16*)wqh_p, (const __nv_bfloat16*)wql_p,
            b_qkv, nullptr,
            (__nv_bfloat16*)qh_p, (__nv_bfloat16*)ql_p, C3);
    }
    // 4) HMMA flash attention (Br=128, exp2 domain, 3-stage KV) -> y hi/lo
    {
        dim3 grid(Tt / 128, Bb * Hh);
        flash_mma<<<grid, 256, FLASH_SMEM>>>(
            (const __nv_bfloat16*)qh_p, (const __nv_bfloat16*)ql_p,
            (__nv_bfloat16*)yh_p, (__nv_bfloat16*)yl_p);
    }
    // 5) Output projection -> out fp32
    {
        dim3 grid(Cc / 128, BT / 128);
        gemm_mma<0><<<grid, 256, GEMM_SMEM>>>(
            (const __nv_bfloat16*)yh_p, (const __nv_bfloat16*)yl_p,
            (const __nv_bfloat16*)wph_p, (const __nv_bfloat16*)wpl_p,
            b_proj, out, nullptr, nullptr, Cc);
    }
}

// round 16
// speedup vs baseline: 1.5515x; 1.5515x over previous
#include <cuda_runtime.h>
#include <cuda_bf16.h>
#include <cstdint>
#include <math.h>

// Problem constants
#define Bb 4
#define Tt 2048
#define Cc 1024
#define Hh 16
#define Dd 64
#define BT (Bb*Tt)          // 8192
#define C3 (3*Cc)           // 3072

// 0.125 * log2(e): folded into K so softmax runs in exp2 domain
#define KSCALE 0.18033688011112042f

// ---------------------------------------------------------------------------
// Scratch (no cudaMalloc allowed)
// ---------------------------------------------------------------------------
__device__ __nv_bfloat16 g_qkvh[BT * C3];        // roped qkv hi (K pre-scaled)
__device__ __nv_bfloat16 g_qkvl[BT * C3];        // roped qkv lo
__device__ __nv_bfloat16 g_xhi[BT * Cc];         // x split
__device__ __nv_bfloat16 g_xlo[BT * Cc];
__device__ __nv_bfloat16 g_wq_hi[C3 * Cc];       // W_qkv^T split  [N=3072][K=1024]
__device__ __nv_bfloat16 g_wq_lo[C3 * Cc];
__device__ __nv_bfloat16 g_wp_hi[Cc * Cc];       // W_proj^T split [N=1024][K=1024]
__device__ __nv_bfloat16 g_wp_lo[Cc * Cc];
__device__ __nv_bfloat16 g_yhi[BT * Cc];         // attention out split
__device__ __nv_bfloat16 g_ylo[BT * Cc];
__device__ float2 g_rope[Tt * 32];               // (sin, cos) per (t, i)

// ---------------------------------------------------------------------------
// Warp MMA helpers (plain sm_80+ features — no arch-suffix gating)
// ---------------------------------------------------------------------------
__device__ __forceinline__ uint32_t smem_to_u32(const void* p) {
    uint32_t a;
    asm("{ .reg .u64 t; cvta.to.shared.u64 t, %1; cvt.u32.u64 %0, t; }"
        : "=r"(a) : "l"(p));
    return a;
}
__device__ __forceinline__ void cp16(uint32_t d, const void* s) {
    asm volatile("cp.async.cg.shared.global [%0], [%1], 16;\n"
                 :: "r"(d), "l"(s) : "memory");
}
#define CP_COMMIT() asm volatile("cp.async.commit_group;" ::: "memory")
#define CP_WAIT(n)  asm volatile("cp.async.wait_group %0;" :: "n"(n) : "memory")

__device__ __forceinline__ void ldm_x4(uint32_t* r, uint32_t addr) {
    asm volatile("ldmatrix.sync.aligned.m8n8.x4.shared.b16 {%0,%1,%2,%3}, [%4];"
                 : "=r"(r[0]), "=r"(r[1]), "=r"(r[2]), "=r"(r[3]) : "r"(addr));
}
__device__ __forceinline__ void ldm_x4_t(uint32_t* r, uint32_t addr) {
    asm volatile("ldmatrix.sync.aligned.m8n8.x4.trans.shared.b16 {%0,%1,%2,%3}, [%4];"
                 : "=r"(r[0]), "=r"(r[1]), "=r"(r[2]), "=r"(r[3]) : "r"(addr));
}
__device__ __forceinline__ void mma_bf16(float* d, const uint32_t* a,
                                         const uint32_t* b) {
    asm volatile(
        "mma.sync.aligned.m16n8k16.row.col.f32.bf16.bf16.f32 "
        "{%0,%1,%2,%3}, {%4,%5,%6,%7}, {%8,%9}, {%0,%1,%2,%3};"
        : "+f"(d[0]), "+f"(d[1]), "+f"(d[2]), "+f"(d[3])
        : "r"(a[0]), "r"(a[1]), "r"(a[2]), "r"(a[3]), "r"(b[0]), "r"(b[1]));
}
// split two floats into packed bf16x2 hi + lo (residual)
__device__ __forceinline__ void split2(float a, float b, uint32_t& hi, uint32_t& lo) {
    __nv_bfloat16 ha = __float2bfloat16(a), hb = __float2bfloat16(b);
    __nv_bfloat16 la = __float2bfloat16(a - __bfloat162float(ha));
    __nv_bfloat16 lb = __float2bfloat16(b - __bfloat162float(hb));
    __nv_bfloat162 h2(ha, hb), l2(la, lb);
    hi = *(uint32_t*)&h2;
    lo = *(uint32_t*)&l2;
}

// ---------------------------------------------------------------------------
// RoPE sin/cos table
// ---------------------------------------------------------------------------
__global__ void fill_rope() {
    int idx = blockIdx.x * blockDim.x + threadIdx.x;
    if (idx >= Tt * 32) return;
    int t = idx >> 5, i = idx & 31;
    float freq = exp2f(-(float)i * 0.4152410118609203f);
    float sn, cs;
    sincosf((float)t * freq, &sn, &cs);
    g_rope[idx] = make_float2(sn, cs);
}

// ---------------------------------------------------------------------------
// Split-bf16 HMMA GEMM (R9 mainloop — known good).
// MODE 0: out = fp32 + bias.
// MODE 1: rope(acc+bias); K section additionally scaled by KSCALE; bf16 hi/lo.
// ---------------------------------------------------------------------------
#define GPITCH 64
#define GSEC   8192
#define GSTAGE (4 * GSEC)
#define GEMM_SMEM (3 * GSTAGE)         // 98304

template<int MODE>
__global__ __launch_bounds__(256, 2) void gemm_mma(
    const __nv_bfloat16* __restrict__ Ahi, const __nv_bfloat16* __restrict__ Alo,
    const __nv_bfloat16* __restrict__ Bhi, const __nv_bfloat16* __restrict__ Blo,
    const float* __restrict__ bias, float* __restrict__ outF,
    __nv_bfloat16* __restrict__ outH, __nv_bfloat16* __restrict__ outL, int N)
{
    extern __shared__ char sm[];
    const int tid = threadIdx.x, lane = tid & 31, wid = tid >> 5;
    const int warpM = wid >> 1, warpN = wid & 1;
    const int mBase = blockIdx.y * 128, nBase = blockIdx.x * 128;
    const uint32_t smBase = smem_to_u32(sm);

    const int aRow = warpM * 32 + (lane & 15);
    const int aSel = (lane >> 4) & 1;
    const int aSwz = ((lane & 15) >> 1) & 3;
    const int bRow = warpN * 64 + (lane & 7) + ((lane >> 4) & 1) * 8;
    const int bSel = (lane >> 3) & 1;
    const int bSwz = ((((lane & 7) + ((lane >> 4) & 1) * 8)) >> 1) & 3;

    float acc[2][8][4];
    #pragma unroll
    for (int a = 0; a < 2; a++)
        #pragma unroll
        for (int q = 0; q < 8; q++)
            #pragma unroll
            for (int v = 0; v < 4; v++) acc[a][q][v] = 0.f;

    auto ldChunk = [&](int c, int stage) {
        uint32_t base = smBase + stage * GSTAGE;
        const int k0 = c * 32;
        #pragma unroll
        for (int i = 0; i < 2; i++) {
            int idx = i * 256 + tid;
            int row = idx >> 2, s = idx & 3;
            int ps = s ^ ((row >> 1) & 3);
            uint32_t d = base + row * GPITCH + ps * 16;
            size_t ga = (size_t)(mBase + row) * 1024 + k0 + s * 8;
            size_t gb = (size_t)(nBase + row) * 1024 + k0 + s * 8;
            cp16(d,            Ahi + ga);
            cp16(d + GSEC,     Alo + ga);
            cp16(d + 2 * GSEC, Bhi + gb);
            cp16(d + 3 * GSEC, Blo + gb);
        }
    };

    auto compute = [&](int stage) {
        uint32_t base = smBase + stage * GSTAGE;
        #pragma unroll
        for (int k16 = 0; k16 < 2; k16++) {
            const int aC = ((k16 * 2 + aSel) ^ aSwz) * 16;
            const int bC = ((k16 * 2 + bSel) ^ bSwz) * 16;
            uint32_t ah[2][4], al[2][4];
            #pragma unroll
            for (int a = 0; a < 2; a++) {
                uint32_t ad = base + (aRow + a * 16) * GPITCH + aC;
                ldm_x4(ah[a], ad);
                ldm_x4(al[a], ad + GSEC);
            }
            #pragma unroll
            for (int p = 0; p < 4; p++) {
                uint32_t bh[4], bl[4];
                uint32_t bd = base + 2 * GSEC + (bRow + p * 16) * GPITCH + bC;
                ldm_x4(bh, bd);
                ldm_x4(bl, bd + GSEC);
                #pragma unroll
                for (int a = 0; a < 2; a++) {
                    mma_bf16(acc[a][p * 2 + 0], ah[a], bh);
                    mma_bf16(acc[a][p * 2 + 0], ah[a], bl);
                    mma_bf16(acc[a][p * 2 + 0], al[a], bh);
                    mma_bf16(acc[a][p * 2 + 1], ah[a], bh + 2);
                    mma_bf16(acc[a][p * 2 + 1], ah[a], bl + 2);
                    mma_bf16(acc[a][p * 2 + 1], al[a], bh + 2);
                }
            }
        }
    };

    ldChunk(0, 0); CP_COMMIT();
    ldChunk(1, 1); CP_COMMIT();
    #pragma unroll 1
    for (int c = 0; c < 32; c++) {
        if (c == 31) { CP_WAIT(0); } else { CP_WAIT(1); }
        __syncthreads();
        if (c + 2 < 32) {
            ldChunk(c + 2, (c + 2) % 3);
            CP_COMMIT();
        }
        compute(c % 3);
    }

    const int r0 = mBase + warpM * 32 + (lane >> 2);
    #pragma unroll
    for (int a = 0; a < 2; a++)
        #pragma unroll
        for (int p = 0; p < 4; p++)
            #pragma unroll
            for (int h = 0; h < 2; h++) {
                const int col = nBase + warpN * 64 + p * 16 + h * 8 + (lane & 3) * 2;
                float2 bb = *(const float2*)(bias + col);
                #pragma unroll
                for (int r = 0; r < 2; r++) {
                    const int row = r0 + a * 16 + r * 8;
                    float v0 = acc[a][p * 2 + h][2 * r]     + bb.x;
                    float v1 = acc[a][p * 2 + h][2 * r + 1] + bb.y;
                    if (MODE == 1) {
                        if (col < 2048) {   // q or k: RoPE
                            int i = (col & 63) >> 1;
                            int t = row & (Tt - 1);
                            float2 sc = g_rope[t * 32 + i];
                            float u0 = v0 * sc.y - v1 * sc.x;
                            float u1 = v0 * sc.x + v1 * sc.y;
                            v0 = u0; v1 = u1;
                            if (col >= 1024) {   // k: fold softmax scale (exp2 domain)
                                v0 *= KSCALE; v1 *= KSCALE;
                            }
                        }
                        uint32_t hi, lo;
                        split2(v0, v1, hi, lo);
                        size_t off = (size_t)row * N + col;
                        *(uint32_t*)(outH + off) = hi;
                        *(uint32_t*)(outL + off) = lo;
                    } else {
                        float2 o = { v0, v1 };
                        *(float2*)(outF + (size_t)row * N + col) = o;
                    }
                }
            }
}

// ---------------------------------------------------------------------------
// HMMA flash attention — EXACT R14 shape (2-stage KV, static addressing).
// Br=128, Bc=64, 256 threads, 2 CTAs/SM. S in exp2 domain. Full 3-combo PV.
// ---------------------------------------------------------------------------
#define FP 144
#define FQSZ (128 * FP)               // 18432
#define FKSZ (64 * FP)                // 9216
#define FKV  (4 * FKSZ)               // 36864 per stage
#define FLASH_SMEM (2 * FQSZ + 2 * FKV)   // 110592

__global__ __launch_bounds__(256, 2) void flash_mma(
    const __nv_bfloat16* __restrict__ qh, const __nv_bfloat16* __restrict__ ql,
    __nv_bfloat16* __restrict__ yh, __nv_bfloat16* __restrict__ yl)
{
    extern __shared__ char sm[];
    const int tid = threadIdx.x, lane = tid & 31, wid = tid >> 5;
    const int bh = blockIdx.y, b = bh >> 4, h = bh & 15;
    const int qt = (gridDim.x - 1) - blockIdx.x;   // heavy CTAs first
    const int q0 = qt * 128;
    const int ntiles = 2 * qt + 2;
    const size_t grow = (size_t)b * Tt;

    const uint32_t QH = smem_to_u32(sm);
    const uint32_t KV0 = QH + 2 * FQSZ;

    {
        #pragma unroll
        for (int i = 0; i < 4; i++) {
            int idx = i * 256 + tid;
            int row = idx >> 3, ch = idx & 7;
            uint32_t d = QH + row * FP + ch * 16;
            size_t src = (grow + q0 + row) * C3 + h * Dd + ch * 8;
            cp16(d,        qh + src);
            cp16(d + FQSZ, ql + src);
        }
    }
    auto prefetchKV = [&](int kt, int buf) {
        uint32_t base = KV0 + buf * FKV;
        #pragma unroll
        for (int i = 0; i < 2; i++) {
            int idx = i * 256 + tid;
            int row = idx >> 3, ch = idx & 7;
            uint32_t d = base + row * FP + ch * 16;
            size_t srcK = (grow + kt * 64 + row) * C3 + Cc + h * Dd + ch * 8;
            size_t srcV = srcK + Cc;
            cp16(d,            qh + srcK);
            cp16(d + FKSZ,     ql + srcK);
            cp16(d + 2 * FKSZ, qh + srcV);
            cp16(d + 3 * FKSZ, ql + srcV);
        }
    };
    prefetchKV(0, 0);
    CP_COMMIT();
    CP_WAIT(0);
    __syncthreads();

    uint32_t qhf[4][4], qlf[4][4];
    {
        uint32_t a = QH + (wid * 16 + (lane & 15)) * FP + ((lane >> 4) & 1) * 16;
        #pragma unroll
        for (int k16 = 0; k16 < 4; k16++) {
            ldm_x4(qhf[k16], a + k16 * 32);
            ldm_x4(qlf[k16], a + FQSZ + k16 * 32);
        }
    }

    float o[8][4];
    float mrow[2] = {-1e30f, -1e30f}, lrow[2] = {0.f, 0.f};
    #pragma unroll
    for (int d = 0; d < 8; d++)
        #pragma unroll
        for (int v = 0; v < 4; v++) o[d][v] = 0.f;

    const int rowMin = q0 + wid * 16;
    const int row0g = rowMin + (lane >> 2);

    #pragma unroll 1
    for (int kt = 0; kt < ntiles; kt++) {
        const int buf = kt & 1;
        if (kt > 0) { CP_WAIT(0); __syncthreads(); }
        if (kt + 1 < ntiles) { prefetchKV(kt + 1, buf ^ 1); CP_COMMIT(); }

        if (kt * 64 > rowMin + 15) continue;   // fully masked for this warp

        const uint32_t KB = KV0 + buf * FKV;

        // ---- S = Q K^T (split; S already in exp2 domain) ----
        float s[8][4];
        #pragma unroll
        for (int n = 0; n < 8; n++)
            #pragma unroll
            for (int v = 0; v < 4; v++) s[n][v] = 0.f;

        #pragma unroll
        for (int k16 = 0; k16 < 4; k16++) {
            #pragma unroll
            for (int np = 0; np < 4; np++) {
                uint32_t kh4[4], kl4[4];
                uint32_t ad = KB + (np * 16 + (lane & 7) + ((lane >> 4) & 1) * 8) * FP
                            + ((lane >> 3) & 1) * 16 + k16 * 32;
                ldm_x4(kh4, ad);
                ldm_x4(kl4, ad + FKSZ);
                mma_bf16(s[2 * np],     qhf[k16], kh4);
                mma_bf16(s[2 * np],     qhf[k16], kl4);
                mma_bf16(s[2 * np],     qlf[k16], kh4);
                mma_bf16(s[2 * np + 1], qhf[k16], kh4 + 2);
                mma_bf16(s[2 * np + 1], qhf[k16], kl4 + 2);
                mma_bf16(s[2 * np + 1], qlf[k16], kh4 + 2);
            }
        }

        // ---- causal mask ----
        if (kt * 64 + 63 > rowMin) {
            #pragma unroll
            for (int n = 0; n < 8; n++) {
                int colg = kt * 64 + n * 8 + (lane & 3) * 2;
                #pragma unroll
                for (int r = 0; r < 2; r++)
                    #pragma unroll
                    for (int j = 0; j < 2; j++)
                        if (colg + j > row0g + r * 8) s[n][2 * r + j] = -1e30f;
            }
        }

        // ---- online softmax in exp2 domain ----
        #pragma unroll
        for (int r = 0; r < 2; r++) {
            float mx = -1e30f;
            #pragma unroll
            for (int n = 0; n < 8; n++)
                mx = fmaxf(mx, fmaxf(s[n][2 * r], s[n][2 * r + 1]));
            mx = fmaxf(mx, __shfl_xor_sync(0xffffffffu, mx, 1));
            mx = fmaxf(mx, __shfl_xor_sync(0xffffffffu, mx, 2));
            float mnew = fmaxf(mrow[r], mx);
            float alpha = exp2f(mrow[r] - mnew);
            float sum = 0.f;
            #pragma unroll
            for (int n = 0; n < 8; n++) {
                float p0 = exp2f(s[n][2 * r] - mnew);
                float p1 = exp2f(s[n][2 * r + 1] - mnew);
                s[n][2 * r] = p0; s[n][2 * r + 1] = p1;
                sum += p0 + p1;
            }
            sum += __shfl_xor_sync(0xffffffffu, sum, 1);
            sum += __shfl_xor_sync(0xffffffffu, sum, 2);
            lrow[r] = lrow[r] * alpha + sum;
            mrow[r] = mnew;
            #pragma unroll
            for (int d = 0; d < 8; d++) {
                o[d][2 * r] *= alpha;
                o[d][2 * r + 1] *= alpha;
            }
        }

        // ---- O += P V (full 3-combo split) ----
        #pragma unroll
        for (int k16 = 0; k16 < 4; k16++) {
            uint32_t phi[4], plo[4];
            const int t0 = 2 * k16, t1 = t0 + 1;
            split2(s[t0][0], s[t0][1], phi[0], plo[0]);
            split2(s[t0][2], s[t0][3], phi[1], plo[1]);
            split2(s[t1][0], s[t1][1], phi[2], plo[2]);
            split2(s[t1][2], s[t1][3], phi[3], plo[3]);
            #pragma unroll
            for (int dp = 0; dp < 4; dp++) {
                uint32_t vh4[4], vl4[4];
                uint32_t ad = KB + 2 * FKSZ
                            + (k16 * 16 + (lane & 7) + ((lane >> 3) & 1) * 8) * FP
                            + ((lane >> 4) & 1) * 16 + dp * 32;
                ldm_x4_t(vh4, ad);
                ldm_x4_t(vl4, ad + FKSZ);
                mma_bf16(o[2 * dp],     phi, vh4);
                mma_bf16(o[2 * dp],     phi, vl4);
                mma_bf16(o[2 * dp],     plo, vh4);
                mma_bf16(o[2 * dp + 1], phi, vh4 + 2);
                mma_bf16(o[2 * dp + 1], phi, vl4 + 2);
                mma_bf16(o[2 * dp + 1], plo, vh4 + 2);
            }
        }
    }

    // ---- epilogue ----
    #pragma unroll
    for (int r = 0; r < 2; r++) {
        const int t = q0 + wid * 16 + (lane >> 2) + r * 8;
        const float inv = 1.f / lrow[r];
        const size_t ro = (grow + t) * Cc + h * Dd;
        #pragma unroll
        for (int d = 0; d < 8; d++) {
            int col = d * 8 + (lane & 3) * 2;
            float v0 = o[d][2 * r] * inv;
            float v1 = o[d][2 * r + 1] * inv;
            uint32_t hi, lo;
            split2(v0, v1, hi, lo);
            *(uint32_t*)(yh + ro + col) = hi;
            *(uint32_t*)(yl + ro + col) = lo;
        }
    }
}

// ---------------------------------------------------------------------------
// fp32 -> (hi, lo) bf16 split
// ---------------------------------------------------------------------------
__global__ __launch_bounds__(256) void split_bf16(
    const float* __restrict__ x, __nv_bfloat16* __restrict__ hi,
    __nv_bfloat16* __restrict__ lo, int n4)
{
    int i = blockIdx.x * blockDim.x + threadIdx.x;
    if (i >= n4) return;
    float4 v = ((const float4*)x)[i];
    __nv_bfloat16 h0 = __float2bfloat16(v.x);
    __nv_bfloat16 h1 = __float2bfloat16(v.y);
    __nv_bfloat16 h2 = __float2bfloat16(v.z);
    __nv_bfloat16 h3 = __float2bfloat16(v.w);
    __nv_bfloat16 l0 = __float2bfloat16(v.x - __bfloat162float(h0));
    __nv_bfloat16 l1 = __float2bfloat16(v.y - __bfloat162float(h1));
    __nv_bfloat16 l2 = __float2bfloat16(v.z - __bfloat162float(h2));
    __nv_bfloat16 l3 = __float2bfloat16(v.w - __bfloat162float(h3));
    __nv_bfloat162* hp = (__nv_bfloat162*)(hi + i * 4);
    __nv_bfloat162* lp = (__nv_bfloat162*)(lo + i * 4);
    hp[0] = __nv_bfloat162(h0, h1); hp[1] = __nv_bfloat162(h2, h3);
    lp[0] = __nv_bfloat162(l0, l1); lp[1] = __nv_bfloat162(l2, l3);
}

// ---------------------------------------------------------------------------
// Both weights: W [K=1024, N] fp32 -> Wt hi/lo bf16 [N, K] transpose + split.
// blockIdx.y < 96 handles W_qkv (N=3072); else W_proj (N=1024).
// ---------------------------------------------------------------------------
__global__ __launch_bounds__(256) void transpose_split_all(
    const float* __restrict__ Wq, const float* __restrict__ Wp,
    __nv_bfloat16* __restrict__ qthi, __nv_bfloat16* __restrict__ qtlo,
    __nv_bfloat16* __restrict__ pthi, __nv_bfloat16* __restrict__ ptlo)
{
    __shared__ float t[32][33];
    const bool isQ = blockIdx.x < (C3 / 32);
    const float* W = isQ ? Wq : Wp;
    __nv_bfloat16* thi = isQ ? qthi : pthi;
    __nv_bfloat16* tlo = isQ ? qtlo : ptlo;
    const int N = isQ ? C3 : Cc;
    const int n0 = (isQ ? blockIdx.x : (blockIdx.x - C3 / 32)) * 32;
    const int k0 = blockIdx.y * 32;
    const int x = threadIdx.x, y = threadIdx.y;   // block (32, 8)
    #pragma unroll
    for (int r = 0; r < 32; r += 8)
        t[y + r][x] = W[(size_t)(k0 + y + r) * N + n0 + x];
    __syncthreads();
    #pragma unroll
    for (int r = 0; r < 32; r += 8) {
        float v = t[x][y + r];
        __nv_bfloat16 h = __float2bfloat16(v);
        __nv_bfloat16 l = __float2bfloat16(v - __bfloat162float(h));
        size_t o = (size_t)(n0 + y + r) * Cc + k0 + x;
        thi[o] = h; tlo[o] = l;
    }
}

// ---------------------------------------------------------------------------
extern "C" void kernel_launch(void* const* d_in, const int* in_sizes, int n_in,
                              void* d_out, int out_size)
{
    const float* x      = (const float*)d_in[0];
    const float* W_qkv  = (const float*)d_in[1];
    const float* b_qkv  = (const float*)d_in[2];
    const float* W_proj = (const float*)d_in[3];
    const float* b_proj = (const float*)d_in[4];
    float* out = (float*)d_out;

    void *qh_p, *ql_p, *xh_p, *xl_p, *wqh_p, *wql_p, *wph_p, *wpl_p,
         *yh_p, *yl_p;
    cudaGetSymbolAddress(&qh_p, g_qkvh);
    cudaGetSymbolAddress(&ql_p, g_qkvl);
    cudaGetSymbolAddress(&xh_p, g_xhi);
    cudaGetSymbolAddress(&xl_p, g_xlo);
    cudaGetSymbolAddress(&wqh_p, g_wq_hi);
    cudaGetSymbolAddress(&wql_p, g_wq_lo);
    cudaGetSymbolAddress(&wph_p, g_wp_hi);
    cudaGetSymbolAddress(&wpl_p, g_wp_lo);
    cudaGetSymbolAddress(&yh_p, g_yhi);
    cudaGetSymbolAddress(&yl_p, g_ylo);

    cudaFuncSetAttribute(gemm_mma<0>,
        cudaFuncAttributeMaxDynamicSharedMemorySize, GEMM_SMEM);
    cudaFuncSetAttribute(gemm_mma<1>,
        cudaFuncAttributeMaxDynamicSharedMemorySize, GEMM_SMEM);
    cudaFuncSetAttribute(flash_mma,
        cudaFuncAttributeMaxDynamicSharedMemorySize, FLASH_SMEM);

    // 0) RoPE sin/cos table
    fill_rope<<<(Tt * 32 + 255) / 256, 256>>>();
    // 1) Split x -> bf16 hi/lo
    split_bf16<<<(BT * Cc / 4 + 255) / 256, 256>>>(
        x, (__nv_bfloat16*)xh_p, (__nv_bfloat16*)xl_p, BT * Cc / 4);
    // 2) Transpose+split both weights (single launch)
    {
        dim3 g(C3 / 32 + Cc / 32, Cc / 32);
        transpose_split_all<<<g, dim3(32, 8)>>>(W_qkv, W_proj,
            (__nv_bfloat16*)wqh_p, (__nv_bfloat16*)wql_p,
            (__nv_bfloat16*)wph_p, (__nv_bfloat16*)wpl_p);
    }
    // 3) QKV GEMM + fused RoPE + K-scale + split -> qkvh/qkvl bf16
    {
        dim3 grid(C3 / 128, BT / 128);
        gemm_mma<1><<<grid, 256, GEMM_SMEM>>>(
            (const __nv_bfloat16*)xh_p, (const __nv_bfloat16*)xl_p,
            (const __nv_bfloat16*)wqh_p, (const __nv_bfloat16*)wql_p,
            b_qkv, nullptr,
            (__nv_bfloat16*)qh_p, (__nv_bfloat16*)ql_p, C3);
    }
    // 4) HMMA flash attention (Br=128, exp2 domain, R14 shape) -> y hi/lo
    {
        dim3 grid(Tt / 128, Bb * Hh);
        flash_mma<<<grid, 256, FLASH_SMEM>>>(
            (const __nv_bfloat16*)qh_p, (const __nv_bfloat16*)ql_p,
            (__nv_bfloat16*)yh_p, (__nv_bfloat16*)yl_p);
    }
    // 5) Output projection -> out fp32
    {
        dim3 grid(Cc / 128, BT / 128);
        gemm_mma<0><<<grid, 256, GEMM_SMEM>>>(
            (const __nv_bfloat16*)yh_p, (const __nv_bfloat16*)yl_p,
            (const __nv_bfloat16*)wph_p, (const __nv_bfloat16*)wpl_p,
            b_proj, out, nullptr, nullptr, Cc);
    }
}

// round 17
// speedup vs baseline: 1.8955x; 1.2217x over previous
#include <cuda_runtime.h>
#include <cuda_bf16.h>
#include <cuda_fp16.h>
#include <cstdint>
#include <math.h>

// Problem constants
#define Bb 4
#define Tt 2048
#define Cc 1024
#define Hh 16
#define Dd 64
#define BT (Bb*Tt)          // 8192
#define C3 (3*Cc)           // 3072

// 0.125 * log2(e): folded into K so softmax runs in exp2 domain
#define KSCALE 0.18033688011112042f

// ---------------------------------------------------------------------------
// Scratch (no cudaMalloc allowed)
// ---------------------------------------------------------------------------
__device__ __nv_bfloat16 g_qkvh[BT * C3];        // roped qkv hi (K pre-scaled)
__device__ __nv_bfloat16 g_qkvl[BT * C3];        // roped qkv lo
__device__ __half g_xhi[BT * Cc];                // x split (fp16 hi/lo)
__device__ __half g_xlo[BT * Cc];
__device__ __half g_wq[C3 * Cc];                 // W_qkv^T fp16 [N=3072][K=1024]
__device__ __half g_wp[Cc * Cc];                 // W_proj^T fp16 [N=1024][K=1024]
__device__ __half g_yhi[BT * Cc];                // attention out split (fp16)
__device__ __half g_ylo[BT * Cc];
__device__ float2 g_rope[Tt * 32];               // (sin, cos) per (t, i)

// ---------------------------------------------------------------------------
// Warp MMA helpers (plain sm_80+ features — no arch-suffix gating)
// ---------------------------------------------------------------------------
__device__ __forceinline__ uint32_t smem_to_u32(const void* p) {
    uint32_t a;
    asm("{ .reg .u64 t; cvta.to.shared.u64 t, %1; cvt.u32.u64 %0, t; }"
        : "=r"(a) : "l"(p));
    return a;
}
__device__ __forceinline__ void cp16(uint32_t d, const void* s) {
    asm volatile("cp.async.cg.shared.global [%0], [%1], 16;\n"
                 :: "r"(d), "l"(s) : "memory");
}
#define CP_COMMIT() asm volatile("cp.async.commit_group;" ::: "memory")
#define CP_WAIT(n)  asm volatile("cp.async.wait_group %0;" :: "n"(n) : "memory")

__device__ __forceinline__ void ldm_x4(uint32_t* r, uint32_t addr) {
    asm volatile("ldmatrix.sync.aligned.m8n8.x4.shared.b16 {%0,%1,%2,%3}, [%4];"
                 : "=r"(r[0]), "=r"(r[1]), "=r"(r[2]), "=r"(r[3]) : "r"(addr));
}
__device__ __forceinline__ void ldm_x4_t(uint32_t* r, uint32_t addr) {
    asm volatile("ldmatrix.sync.aligned.m8n8.x4.trans.shared.b16 {%0,%1,%2,%3}, [%4];"
                 : "=r"(r[0]), "=r"(r[1]), "=r"(r[2]), "=r"(r[3]) : "r"(addr));
}
__device__ __forceinline__ void mma_bf16(float* d, const uint32_t* a,
                                         const uint32_t* b) {
    asm volatile(
        "mma.sync.aligned.m16n8k16.row.col.f32.bf16.bf16.f32 "
        "{%0,%1,%2,%3}, {%4,%5,%6,%7}, {%8,%9}, {%0,%1,%2,%3};"
        : "+f"(d[0]), "+f"(d[1]), "+f"(d[2]), "+f"(d[3])
        : "r"(a[0]), "r"(a[1]), "r"(a[2]), "r"(a[3]), "r"(b[0]), "r"(b[1]));
}
__device__ __forceinline__ void mma_f16(float* d, const uint32_t* a,
                                        const uint32_t* b) {
    asm volatile(
        "mma.sync.aligned.m16n8k16.row.col.f32.f16.f16.f32 "
        "{%0,%1,%2,%3}, {%4,%5,%6,%7}, {%8,%9}, {%0,%1,%2,%3};"
        : "+f"(d[0]), "+f"(d[1]), "+f"(d[2]), "+f"(d[3])
        : "r"(a[0]), "r"(a[1]), "r"(a[2]), "r"(a[3]), "r"(b[0]), "r"(b[1]));
}
// split two floats into packed bf16x2 hi + lo (residual)
__device__ __forceinline__ void split2(float a, float b, uint32_t& hi, uint32_t& lo) {
    __nv_bfloat16 ha = __float2bfloat16(a), hb = __float2bfloat16(b);
    __nv_bfloat16 la = __float2bfloat16(a - __bfloat162float(ha));
    __nv_bfloat16 lb = __float2bfloat16(b - __bfloat162float(hb));
    __nv_bfloat162 h2(ha, hb), l2(la, lb);
    hi = *(uint32_t*)&h2;
    lo = *(uint32_t*)&l2;
}
// split two floats into packed fp16x2 hi + lo (residual)
__device__ __forceinline__ void split2h(float a, float b, uint32_t& hi, uint32_t& lo) {
    __half ha = __float2half_rn(a), hb = __float2half_rn(b);
    __half la = __float2half_rn(a - __half2float(ha));
    __half lb = __float2half_rn(b - __half2float(hb));
    __half2 h2(ha, hb), l2(la, lb);
    hi = *(uint32_t*)&h2;
    lo = *(uint32_t*)&l2;
}

// ---------------------------------------------------------------------------
// RoPE sin/cos table
// ---------------------------------------------------------------------------
__global__ void fill_rope() {
    int idx = blockIdx.x * blockDim.x + threadIdx.x;
    if (idx >= Tt * 32) return;
    int t = idx >> 5, i = idx & 31;
    float freq = exp2f(-(float)i * 0.4152410118609203f);
    float sn, cs;
    sincosf((float)t * freq, &sn, &cs);
    g_rope[idx] = make_float2(sn, cs);
}

// ---------------------------------------------------------------------------
// fp16 HMMA GEMM: C = (Ahi + Alo) * B^T, A fp16-split (exact), B fp16 single.
// 2 MMAs per K16 (was 3). Stage = Ahi + Alo + B = 24 KB; 3 stages = 72 KB.
// MODE 0: out = fp32 + bias.
// MODE 1: rope(acc+bias); K section scaled by KSCALE; bf16 hi/lo out (flash fmt)
// ---------------------------------------------------------------------------
#define GPITCH 64
#define GSEC   8192
#define GSTAGE (3 * GSEC)              // 24576: Ahi, Alo, B
#define GEMM_SMEM (3 * GSTAGE)         // 73728

template<int MODE>
__global__ __launch_bounds__(256, 2) void gemm_mma(
    const __half* __restrict__ Ahi, const __half* __restrict__ Alo,
    const __half* __restrict__ Bw,
    const float* __restrict__ bias, float* __restrict__ outF,
    __nv_bfloat16* __restrict__ outH, __nv_bfloat16* __restrict__ outL, int N)
{
    extern __shared__ char sm[];
    const int tid = threadIdx.x, lane = tid & 31, wid = tid >> 5;
    const int warpM = wid >> 1, warpN = wid & 1;
    const int mBase = blockIdx.y * 128, nBase = blockIdx.x * 128;
    const uint32_t smBase = smem_to_u32(sm);

    const int aRow = warpM * 32 + (lane & 15);
    const int aSel = (lane >> 4) & 1;
    const int aSwz = ((lane & 15) >> 1) & 3;
    const int bRow = warpN * 64 + (lane & 7) + ((lane >> 4) & 1) * 8;
    const int bSel = (lane >> 3) & 1;
    const int bSwz = ((((lane & 7) + ((lane >> 4) & 1) * 8)) >> 1) & 3;

    float acc[2][8][4];
    #pragma unroll
    for (int a = 0; a < 2; a++)
        #pragma unroll
        for (int q = 0; q < 8; q++)
            #pragma unroll
            for (int v = 0; v < 4; v++) acc[a][q][v] = 0.f;

    auto ldChunk = [&](int c, int stage) {
        uint32_t base = smBase + stage * GSTAGE;
        const int k0 = c * 32;
        #pragma unroll
        for (int i = 0; i < 2; i++) {
            int idx = i * 256 + tid;
            int row = idx >> 2, s = idx & 3;
            int ps = s ^ ((row >> 1) & 3);
            uint32_t d = base + row * GPITCH + ps * 16;
            size_t ga = (size_t)(mBase + row) * 1024 + k0 + s * 8;
            size_t gb = (size_t)(nBase + row) * 1024 + k0 + s * 8;
            cp16(d,            Ahi + ga);
            cp16(d + GSEC,     Alo + ga);
            cp16(d + 2 * GSEC, Bw  + gb);
        }
    };

    auto compute = [&](int stage) {
        uint32_t base = smBase + stage * GSTAGE;
        #pragma unroll
        for (int k16 = 0; k16 < 2; k16++) {
            const int aC = ((k16 * 2 + aSel) ^ aSwz) * 16;
            const int bC = ((k16 * 2 + bSel) ^ bSwz) * 16;
            uint32_t ah[2][4], al[2][4];
            #pragma unroll
            for (int a = 0; a < 2; a++) {
                uint32_t ad = base + (aRow + a * 16) * GPITCH + aC;
                ldm_x4(ah[a], ad);
                ldm_x4(al[a], ad + GSEC);
            }
            #pragma unroll
            for (int p = 0; p < 4; p++) {
                uint32_t bh[4];
                uint32_t bd = base + 2 * GSEC + (bRow + p * 16) * GPITCH + bC;
                ldm_x4(bh, bd);
                #pragma unroll
                for (int a = 0; a < 2; a++) {
                    mma_f16(acc[a][p * 2 + 0], ah[a], bh);
                    mma_f16(acc[a][p * 2 + 0], al[a], bh);
                    mma_f16(acc[a][p * 2 + 1], ah[a], bh + 2);
                    mma_f16(acc[a][p * 2 + 1], al[a], bh + 2);
                }
            }
        }
    };

    ldChunk(0, 0); CP_COMMIT();
    ldChunk(1, 1); CP_COMMIT();
    #pragma unroll 1
    for (int c = 0; c < 32; c++) {
        if (c == 31) { CP_WAIT(0); } else { CP_WAIT(1); }
        __syncthreads();
        if (c + 2 < 32) {
            ldChunk(c + 2, (c + 2) % 3);
            CP_COMMIT();
        }
        compute(c % 3);
    }

    const int r0 = mBase + warpM * 32 + (lane >> 2);
    #pragma unroll
    for (int a = 0; a < 2; a++)
        #pragma unroll
        for (int p = 0; p < 4; p++)
            #pragma unroll
            for (int h = 0; h < 2; h++) {
                const int col = nBase + warpN * 64 + p * 16 + h * 8 + (lane & 3) * 2;
                float2 bb = *(const float2*)(bias + col);
                #pragma unroll
                for (int r = 0; r < 2; r++) {
                    const int row = r0 + a * 16 + r * 8;
                    float v0 = acc[a][p * 2 + h][2 * r]     + bb.x;
                    float v1 = acc[a][p * 2 + h][2 * r + 1] + bb.y;
                    if (MODE == 1) {
                        if (col < 2048) {   // q or k: RoPE
                            int i = (col & 63) >> 1;
                            int t = row & (Tt - 1);
                            float2 sc = g_rope[t * 32 + i];
                            float u0 = v0 * sc.y - v1 * sc.x;
                            float u1 = v0 * sc.x + v1 * sc.y;
                            v0 = u0; v1 = u1;
                            if (col >= 1024) {   // k: fold softmax scale (exp2)
                                v0 *= KSCALE; v1 *= KSCALE;
                            }
                        }
                        uint32_t hi, lo;
                        split2(v0, v1, hi, lo);
                        size_t off = (size_t)row * N + col;
                        *(uint32_t*)(outH + off) = hi;
                        *(uint32_t*)(outL + off) = lo;
                    } else {
                        float2 o = { v0, v1 };
                        *(float2*)(outF + (size_t)row * N + col) = o;
                    }
                }
            }
}

// ---------------------------------------------------------------------------
// HMMA flash attention — R14 shape (2-stage KV, static addressing).
// Br=128, Bc=64, 256 threads, 2 CTAs/SM. S in exp2 domain. Full 3-combo PV.
// Internals bf16 (proven); OUTPUT y now fp16 hi/lo for the fp16 gemm2.
// ---------------------------------------------------------------------------
#define FP 144
#define FQSZ (128 * FP)               // 18432
#define FKSZ (64 * FP)                // 9216
#define FKV  (4 * FKSZ)               // 36864 per stage
#define FLASH_SMEM (2 * FQSZ + 2 * FKV)   // 110592

__global__ __launch_bounds__(256, 2) void flash_mma(
    const __nv_bfloat16* __restrict__ qh, const __nv_bfloat16* __restrict__ ql,
    __half* __restrict__ yh, __half* __restrict__ yl)
{
    extern __shared__ char sm[];
    const int tid = threadIdx.x, lane = tid & 31, wid = tid >> 5;
    const int bh = blockIdx.y, b = bh >> 4, h = bh & 15;
    const int qt = (gridDim.x - 1) - blockIdx.x;   // heavy CTAs first
    const int q0 = qt * 128;
    const int ntiles = 2 * qt + 2;
    const size_t grow = (size_t)b * Tt;

    const uint32_t QH = smem_to_u32(sm);
    const uint32_t KV0 = QH + 2 * FQSZ;

    {
        #pragma unroll
        for (int i = 0; i < 4; i++) {
            int idx = i * 256 + tid;
            int row = idx >> 3, ch = idx & 7;
            uint32_t d = QH + row * FP + ch * 16;
            size_t src = (grow + q0 + row) * C3 + h * Dd + ch * 8;
            cp16(d,        qh + src);
            cp16(d + FQSZ, ql + src);
        }
    }
    auto prefetchKV = [&](int kt, int buf) {
        uint32_t base = KV0 + buf * FKV;
        #pragma unroll
        for (int i = 0; i < 2; i++) {
            int idx = i * 256 + tid;
            int row = idx >> 3, ch = idx & 7;
            uint32_t d = base + row * FP + ch * 16;
            size_t srcK = (grow + kt * 64 + row) * C3 + Cc + h * Dd + ch * 8;
            size_t srcV = srcK + Cc;
            cp16(d,            qh + srcK);
            cp16(d + FKSZ,     ql + srcK);
            cp16(d + 2 * FKSZ, qh + srcV);
            cp16(d + 3 * FKSZ, ql + srcV);
        }
    };
    prefetchKV(0, 0);
    CP_COMMIT();
    CP_WAIT(0);
    __syncthreads();

    uint32_t qhf[4][4], qlf[4][4];
    {
        uint32_t a = QH + (wid * 16 + (lane & 15)) * FP + ((lane >> 4) & 1) * 16;
        #pragma unroll
        for (int k16 = 0; k16 < 4; k16++) {
            ldm_x4(qhf[k16], a + k16 * 32);
            ldm_x4(qlf[k16], a + FQSZ + k16 * 32);
        }
    }

    float o[8][4];
    float mrow[2] = {-1e30f, -1e30f}, lrow[2] = {0.f, 0.f};
    #pragma unroll
    for (int d = 0; d < 8; d++)
        #pragma unroll
        for (int v = 0; v < 4; v++) o[d][v] = 0.f;

    const int rowMin = q0 + wid * 16;
    const int row0g = rowMin + (lane >> 2);

    #pragma unroll 1
    for (int kt = 0; kt < ntiles; kt++) {
        const int buf = kt & 1;
        if (kt > 0) { CP_WAIT(0); __syncthreads(); }
        if (kt + 1 < ntiles) { prefetchKV(kt + 1, buf ^ 1); CP_COMMIT(); }

        if (kt * 64 > rowMin + 15) continue;   // fully masked for this warp

        const uint32_t KB = KV0 + buf * FKV;

        // ---- S = Q K^T (split; S already in exp2 domain) ----
        float s[8][4];
        #pragma unroll
        for (int n = 0; n < 8; n++)
            #pragma unroll
            for (int v = 0; v < 4; v++) s[n][v] = 0.f;

        #pragma unroll
        for (int k16 = 0; k16 < 4; k16++) {
            #pragma unroll
            for (int np = 0; np < 4; np++) {
                uint32_t kh4[4], kl4[4];
                uint32_t ad = KB + (np * 16 + (lane & 7) + ((lane >> 4) & 1) * 8) * FP
                            + ((lane >> 3) & 1) * 16 + k16 * 32;
                ldm_x4(kh4, ad);
                ldm_x4(kl4, ad + FKSZ);
                mma_bf16(s[2 * np],     qhf[k16], kh4);
                mma_bf16(s[2 * np],     qhf[k16], kl4);
                mma_bf16(s[2 * np],     qlf[k16], kh4);
                mma_bf16(s[2 * np + 1], qhf[k16], kh4 + 2);
                mma_bf16(s[2 * np + 1], qhf[k16], kl4 + 2);
                mma_bf16(s[2 * np + 1], qlf[k16], kh4 + 2);
            }
        }

        // ---- causal mask ----
        if (kt * 64 + 63 > rowMin) {
            #pragma unroll
            for (int n = 0; n < 8; n++) {
                int colg = kt * 64 + n * 8 + (lane & 3) * 2;
                #pragma unroll
                for (int r = 0; r < 2; r++)
                    #pragma unroll
                    for (int j = 0; j < 2; j++)
                        if (colg + j > row0g + r * 8) s[n][2 * r + j] = -1e30f;
            }
        }

        // ---- online softmax in exp2 domain ----
        #pragma unroll
        for (int r = 0; r < 2; r++) {
            float mx = -1e30f;
            #pragma unroll
            for (int n = 0; n < 8; n++)
                mx = fmaxf(mx, fmaxf(s[n][2 * r], s[n][2 * r + 1]));
            mx = fmaxf(mx, __shfl_xor_sync(0xffffffffu, mx, 1));
            mx = fmaxf(mx, __shfl_xor_sync(0xffffffffu, mx, 2));
            float mnew = fmaxf(mrow[r], mx);
            float alpha = exp2f(mrow[r] - mnew);
            float sum = 0.f;
            #pragma unroll
            for (int n = 0; n < 8; n++) {
                float p0 = exp2f(s[n][2 * r] - mnew);
                float p1 = exp2f(s[n][2 * r + 1] - mnew);
                s[n][2 * r] = p0; s[n][2 * r + 1] = p1;
                sum += p0 + p1;
            }
            sum += __shfl_xor_sync(0xffffffffu, sum, 1);
            sum += __shfl_xor_sync(0xffffffffu, sum, 2);
            lrow[r] = lrow[r] * alpha + sum;
            mrow[r] = mnew;
            #pragma unroll
            for (int d = 0; d < 8; d++) {
                o[d][2 * r] *= alpha;
                o[d][2 * r + 1] *= alpha;
            }
        }

        // ---- O += P V (full 3-combo split) ----
        #pragma unroll
        for (int k16 = 0; k16 < 4; k16++) {
            uint32_t phi[4], plo[4];
            const int t0 = 2 * k16, t1 = t0 + 1;
            split2(s[t0][0], s[t0][1], phi[0], plo[0]);
            split2(s[t0][2], s[t0][3], phi[1], plo[1]);
            split2(s[t1][0], s[t1][1], phi[2], plo[2]);
            split2(s[t1][2], s[t1][3], phi[3], plo[3]);
            #pragma unroll
            for (int dp = 0; dp < 4; dp++) {
                uint32_t vh4[4], vl4[4];
                uint32_t ad = KB + 2 * FKSZ
                            + (k16 * 16 + (lane & 7) + ((lane >> 3) & 1) * 8) * FP
                            + ((lane >> 4) & 1) * 16 + dp * 32;
                ldm_x4_t(vh4, ad);
                ldm_x4_t(vl4, ad + FKSZ);
                mma_bf16(o[2 * dp],     phi, vh4);
                mma_bf16(o[2 * dp],     phi, vl4);
                mma_bf16(o[2 * dp],     plo, vh4);
                mma_bf16(o[2 * dp + 1], phi, vh4 + 2);
                mma_bf16(o[2 * dp + 1], phi, vl4 + 2);
                mma_bf16(o[2 * dp + 1], plo, vh4 + 2);
            }
        }
    }

    // ---- epilogue: fp16 hi/lo output for gemm2 ----
    #pragma unroll
    for (int r = 0; r < 2; r++) {
        const int t = q0 + wid * 16 + (lane >> 2) + r * 8;
        const float inv = 1.f / lrow[r];
        const size_t ro = (grow + t) * Cc + h * Dd;
        #pragma unroll
        for (int d = 0; d < 8; d++) {
            int col = d * 8 + (lane & 3) * 2;
            float v0 = o[d][2 * r] * inv;
            float v1 = o[d][2 * r + 1] * inv;
            uint32_t hi, lo;
            split2h(v0, v1, hi, lo);
            *(uint32_t*)(yh + ro + col) = hi;
            *(uint32_t*)(yl + ro + col) = lo;
        }
    }
}

// ---------------------------------------------------------------------------
// fp32 -> (hi, lo) fp16 split (x)
// ---------------------------------------------------------------------------
__global__ __launch_bounds__(256) void split_fp16(
    const float* __restrict__ x, __half* __restrict__ hi,
    __half* __restrict__ lo, int n4)
{
    int i = blockIdx.x * blockDim.x + threadIdx.x;
    if (i >= n4) return;
    float4 v = ((const float4*)x)[i];
    uint32_t h0, l0, h1, l1;
    split2h(v.x, v.y, h0, l0);
    split2h(v.z, v.w, h1, l1);
    uint32_t* hp = (uint32_t*)(hi + (size_t)i * 4);
    uint32_t* lp = (uint32_t*)(lo + (size_t)i * 4);
    hp[0] = h0; hp[1] = h1;
    lp[0] = l0; lp[1] = l1;
}

// ---------------------------------------------------------------------------
// Both weights: W [K=1024, N] fp32 -> Wt fp16 single [N, K] (transpose)
// ---------------------------------------------------------------------------
__global__ __launch_bounds__(256) void transpose_fp16_all(
    const float* __restrict__ Wq, const float* __restrict__ Wp,
    __half* __restrict__ qt, __half* __restrict__ pt)
{
    __shared__ float t[32][33];
    const bool isQ = blockIdx.x < (C3 / 32);
    const float* W = isQ ? Wq : Wp;
    __half* to = isQ ? qt : pt;
    const int N = isQ ? C3 : Cc;
    const int n0 = (isQ ? blockIdx.x : (blockIdx.x - C3 / 32)) * 32;
    const int k0 = blockIdx.y * 32;
    const int x = threadIdx.x, y = threadIdx.y;   // block (32, 8)
    #pragma unroll
    for (int r = 0; r < 32; r += 8)
        t[y + r][x] = W[(size_t)(k0 + y + r) * N + n0 + x];
    __syncthreads();
    #pragma unroll
    for (int r = 0; r < 32; r += 8) {
        float v = t[x][y + r];
        to[(size_t)(n0 + y + r) * Cc + k0 + x] = __float2half_rn(v);
    }
}

// ---------------------------------------------------------------------------
extern "C" void kernel_launch(void* const* d_in, const int* in_sizes, int n_in,
                              void* d_out, int out_size)
{
    const float* x      = (const float*)d_in[0];
    const float* W_qkv  = (const float*)d_in[1];
    const float* b_qkv  = (const float*)d_in[2];
    const float* W_proj = (const float*)d_in[3];
    const float* b_proj = (const float*)d_in[4];
    float* out = (float*)d_out;

    void *qh_p, *ql_p, *xh_p, *xl_p, *wq_p, *wp_p, *yh_p, *yl_p;
    cudaGetSymbolAddress(&qh_p, g_qkvh);
    cudaGetSymbolAddress(&ql_p, g_qkvl);
    cudaGetSymbolAddress(&xh_p, g_xhi);
    cudaGetSymbolAddress(&xl_p, g_xlo);
    cudaGetSymbolAddress(&wq_p, g_wq);
    cudaGetSymbolAddress(&wp_p, g_wp);
    cudaGetSymbolAddress(&yh_p, g_yhi);
    cudaGetSymbolAddress(&yl_p, g_ylo);

    cudaFuncSetAttribute(gemm_mma<0>,
        cudaFuncAttributeMaxDynamicSharedMemorySize, GEMM_SMEM);
    cudaFuncSetAttribute(gemm_mma<1>,
        cudaFuncAttributeMaxDynamicSharedMemorySize, GEMM_SMEM);
    cudaFuncSetAttribute(flash_mma,
        cudaFuncAttributeMaxDynamicSharedMemorySize, FLASH_SMEM);

    // 0) RoPE sin/cos table
    fill_rope<<<(Tt * 32 + 255) / 256, 256>>>();
    // 1) Split x -> fp16 hi/lo
    split_fp16<<<(BT * Cc / 4 + 255) / 256, 256>>>(
        x, (__half*)xh_p, (__half*)xl_p, BT * Cc / 4);
    // 2) Transpose both weights -> fp16 single
    {
        dim3 g(C3 / 32 + Cc / 32, Cc / 32);
        transpose_fp16_all<<<g, dim3(32, 8)>>>(W_qkv, W_proj,
            (__half*)wq_p, (__half*)wp_p);
    }
    // 3) QKV GEMM (fp16, 2-MMA) + fused RoPE + K-scale -> qkvh/qkvl bf16
    {
        dim3 grid(C3 / 128, BT / 128);
        gemm_mma<1><<<grid, 256, GEMM_SMEM>>>(
            (const __half*)xh_p, (const __half*)xl_p, (const __half*)wq_p,
            b_qkv, nullptr,
            (__nv_bfloat16*)qh_p, (__nv_bfloat16*)ql_p, C3);
    }
    // 4) HMMA flash attention (Br=128, exp2 domain) -> y fp16 hi/lo
    {
        dim3 grid(Tt / 128, Bb * Hh);
        flash_mma<<<grid, 256, FLASH_SMEM>>>(
            (const __nv_bfloat16*)qh_p, (const __nv_bfloat16*)ql_p,
            (__half*)yh_p, (__half*)yl_p);
    }
    // 5) Output projection (fp16, 2-MMA) -> out fp32
    {
        dim3 grid(Cc / 128, BT / 128);
        gemm_mma<0><<<grid, 256, GEMM_SMEM>>>(
            (const __half*)yh_p, (const __half*)yl_p, (const __half*)wp_p,
            b_proj, out, nullptr, nullptr, Cc);
    }
}